// round 2
// baseline (speedup 1.0000x reference)
#include <cuda_runtime.h>
#include <math_constants.h>

// Problem constants (fixed dataset: batch_reprs [4096,128] f32, batch_labels [4096] i32)
#define BSZ 4096
#define DIM 128
#define MARGIN 0.2f
#define MAXK 512      // safe upper bound on per-class count (expected max ~25)

// Scratch (static __device__ — no allocations allowed)
__device__ float g_sim[(size_t)BSZ * BSZ];   // 64 MB sim matrix
__device__ float g_sq[BSZ];
__device__ float g_partial[BSZ];

// ---------------------------------------------------------------------------
// K1: row squared norms
// ---------------------------------------------------------------------------
__global__ void sq_kernel(const float* __restrict__ X) {
    int row = blockIdx.x * 8 + threadIdx.y;
    const float* x = X + row * DIM;
    float s = 0.f;
    for (int c = threadIdx.x; c < DIM; c += 32) {
        float v = x[c];
        s = fmaf(v, v, s);
    }
    #pragma unroll
    for (int o = 16; o; o >>= 1) s += __shfl_down_sync(0xffffffffu, s, o);
    if (threadIdx.x == 0) g_sq[row] = s;
}

// ---------------------------------------------------------------------------
// K2: sim matrix = -sqrt(max(sq_i+sq_j-2*dot,0)) + 0.2*(label mismatch)
// 128x128 tile per CTA, 256 threads, 8x8 per thread, K chunked by 32.
// ---------------------------------------------------------------------------
__global__ void __launch_bounds__(256, 2) sim_kernel(
    const float* __restrict__ X, const int* __restrict__ labels) {
    __shared__ float As[32][132];   // [k][row], padded; 132*4=528 keeps 16B align
    __shared__ float Bs[32][132];

    const int tileR = blockIdx.y * 128;
    const int tileC = blockIdx.x * 128;
    const int tid = threadIdx.x;
    const int tx = tid & 15;        // 16 col-groups
    const int ty = tid >> 4;        // 16 row-groups

    float acc[8][8] = {};

    for (int kk = 0; kk < DIM; kk += 32) {
        #pragma unroll
        for (int e = tid; e < 128 * 32; e += 256) {
            int r = e >> 5, c = e & 31;
            As[c][r] = X[(tileR + r) * DIM + kk + c];
            Bs[c][r] = X[(tileC + r) * DIM + kk + c];
        }
        __syncthreads();
        #pragma unroll
        for (int k = 0; k < 32; k++) {
            float4 a0 = *(const float4*)&As[k][ty * 8];
            float4 a1 = *(const float4*)&As[k][ty * 8 + 4];
            float4 b0 = *(const float4*)&Bs[k][tx * 8];
            float4 b1 = *(const float4*)&Bs[k][tx * 8 + 4];
            float a[8] = {a0.x, a0.y, a0.z, a0.w, a1.x, a1.y, a1.z, a1.w};
            float b[8] = {b0.x, b0.y, b0.z, b0.w, b1.x, b1.y, b1.z, b1.w};
            #pragma unroll
            for (int i = 0; i < 8; i++)
                #pragma unroll
                for (int j = 0; j < 8; j++)
                    acc[i][j] = fmaf(a[i], b[j], acc[i][j]);
        }
        __syncthreads();
    }

    // epilogue
    int   Lc[8];
    float sqc[8];
    #pragma unroll
    for (int j = 0; j < 8; j++) {
        int c = tileC + tx * 8 + j;
        Lc[j]  = __ldg(&labels[c]);
        sqc[j] = __ldg(&g_sq[c]);
    }
    #pragma unroll
    for (int i = 0; i < 8; i++) {
        int r = tileR + ty * 8 + i;
        int Lr = __ldg(&labels[r]);
        float sqr = __ldg(&g_sq[r]);
        float out[8];
        #pragma unroll
        for (int j = 0; j < 8; j++) {
            float d2 = fmaxf(sqr + sqc[j] - 2.0f * acc[i][j], 0.0f);
            float dist = sqrtf(d2);            // d2==0 -> 0, matches reference
            out[j] = -dist + ((Lc[j] != Lr) ? MARGIN : 0.0f);
        }
        float* dst = &g_sim[(size_t)r * BSZ + tileC + tx * 8];
        *(float4*)(dst)     = make_float4(out[0], out[1], out[2], out[3]);
        *(float4*)(dst + 4) = make_float4(out[4], out[5], out[6], out[7]);
    }
}

// ---------------------------------------------------------------------------
// K3: per-row ranking + loss partial. One CTA (256 threads) per row.
// Stable order: sim descending, index ascending (== jnp.argsort semantics).
// Insight: #fn == fp_num always, so ALL false negatives are selected.
// ---------------------------------------------------------------------------
__global__ void __launch_bounds__(256) rank_kernel(const int* __restrict__ labels) {
    constexpr int NT = 256;
    __shared__ float s_sim[BSZ];            // 16 KB
    __shared__ int   s_lab[BSZ];            // 16 KB
    __shared__ int   s_pos[MAXK];
    __shared__ float s_tksim[MAXK];
    __shared__ int   s_tkidx[MAXK];
    __shared__ int   s_fn[MAXK];
    __shared__ int   s_fnrank[MAXK];
    __shared__ float red_f[8];
    __shared__ int   red_i[8];
    __shared__ int   s_cnt;
    __shared__ float s_prevS;
    __shared__ int   s_prevI;
    __shared__ float s_fpterm;
    __shared__ int   s_nfn;

    const int row = blockIdx.x;
    const int tid = threadIdx.x;
    const float* srow = g_sim + (size_t)row * BSZ;

    if (tid == 0) s_cnt = 0;
    for (int j = tid; j < BSZ; j += NT) {
        s_sim[j] = srow[j];
        s_lab[j] = labels[j];
    }
    __syncthreads();

    const int L = s_lab[row];

    // collect positives (unordered), count k
    for (int j = tid; j < BSZ; j += NT) {
        if (s_lab[j] == L) {
            int p = atomicAdd(&s_cnt, 1);
            if (p < MAXK) s_pos[p] = j;
        }
    }
    __syncthreads();
    int k = s_cnt;
    if (k > MAXK) k = MAXK;

    // sort positive list by index (determinism + matches nothing else needed)
    if (tid == 0) {
        for (int a = 1; a < k; a++) {
            int v = s_pos[a], b = a - 1;
            while (b >= 0 && s_pos[b] > v) { s_pos[b + 1] = s_pos[b]; b--; }
            s_pos[b + 1] = v;
        }
    }
    __syncthreads();

    // iterative top-k selection (no mutation: threshold on previous key)
    float prevS = CUDART_INF_F;
    int   prevI = -1;
    for (int r = 0; r < k; r++) {
        float bs = -CUDART_INF_F;
        int   bi = BSZ;
        for (int j = tid; j < BSZ; j += NT) {
            float s = s_sim[j];
            bool ltPrev = (s < prevS) || (s == prevS && j > prevI);
            if (ltPrev && (s > bs || (s == bs && j < bi))) { bs = s; bi = j; }
        }
        #pragma unroll
        for (int o = 16; o; o >>= 1) {
            float os = __shfl_down_sync(0xffffffffu, bs, o);
            int   oi = __shfl_down_sync(0xffffffffu, bi, o);
            if (os > bs || (os == bs && oi < bi)) { bs = os; bi = oi; }
        }
        if ((tid & 31) == 0) { red_f[tid >> 5] = bs; red_i[tid >> 5] = bi; }
        __syncthreads();
        if (tid == 0) {
            for (int w = 1; w < 8; w++) {
                if (red_f[w] > bs || (red_f[w] == bs && red_i[w] < bi)) {
                    bs = red_f[w]; bi = red_i[w];
                }
            }
            s_tksim[r] = bs; s_tkidx[r] = bi;
            s_prevS = bs;    s_prevI = bi;
        }
        __syncthreads();
        prevS = s_prevS;
        prevI = s_prevI;
    }

    // fp_term + false-negative list (serial, k is tiny; deterministic order)
    if (tid == 0) {
        float kf = (float)k;
        float fp_term = 0.0f;
        for (int r = 0; r < k; r++) {
            int j = s_tkidx[r];
            if (s_lab[j] != L) {
                float rank = (float)(r + 1);
                fp_term += s_tksim[r] * (0.5f + (kf - rank + 1.0f) / kf * 0.5f);
            }
        }
        int nfn = 0;
        for (int p = 0; p < k; p++) {
            int j = s_pos[p];
            bool in_topk = false;
            for (int r = 0; r < k; r++)
                if (s_tkidx[r] == j) { in_topk = true; break; }
            if (!in_topk) s_fn[nfn++] = j;
        }
        s_fpterm = fp_term;
        s_nfn = nfn;
    }
    __syncthreads();

    // global rank of each fn positive: 1 + #{sim>s} + #{sim==s && m<j}
    const int nfn = s_nfn;
    for (int q = 0; q < nfn; q++) {
        int j = s_fn[q];
        float s = s_sim[j];
        int c = 0;
        for (int m = tid; m < BSZ; m += NT) {
            float v = s_sim[m];
            c += (v > s) ? 1 : 0;
            c += (v == s && m < j) ? 1 : 0;
        }
        #pragma unroll
        for (int o = 16; o; o >>= 1) c += __shfl_down_sync(0xffffffffu, c, o);
        if ((tid & 31) == 0) red_i[tid >> 5] = c;
        __syncthreads();
        if (tid == 0) {
            int tot = 0;
            for (int w = 0; w < 8; w++) tot += red_i[w];
            s_fnrank[q] = tot + 1;
        }
        __syncthreads();
    }

    if (tid == 0) {
        float kf = (float)k;
        float nk = (float)BSZ - kf;
        float fn_term = 0.0f;
        for (int q = 0; q < nfn; q++) {
            int j = s_fn[q];
            float rank = (float)s_fnrank[q];
            fn_term += s_sim[j] * (0.5f + (rank - kf) / nk * 0.5f);
        }
        g_partial[row] = s_fpterm - fn_term;
    }
}

// ---------------------------------------------------------------------------
// K4: deterministic fixed-order reduction of row partials
// ---------------------------------------------------------------------------
__global__ void reduce_kernel(float* __restrict__ out) {
    __shared__ float s[256];
    int tid = threadIdx.x;
    float a = 0.0f;
    for (int i = tid; i < BSZ; i += 256) a += g_partial[i];
    s[tid] = a;
    __syncthreads();
    for (int o = 128; o; o >>= 1) {
        if (tid < o) s[tid] += s[tid + o];
        __syncthreads();
    }
    if (tid == 0) out[0] = s[0];
}

// ---------------------------------------------------------------------------
extern "C" void kernel_launch(void* const* d_in, const int* in_sizes, int n_in,
                              void* d_out, int out_size) {
    const float* X      = (const float*)d_in[0];   // batch_reprs [4096,128] f32
    const int*   labels = (const int*)d_in[1];     // batch_labels [4096] i32
    float* out = (float*)d_out;

    sq_kernel<<<BSZ / 8, dim3(32, 8)>>>(X);
    sim_kernel<<<dim3(BSZ / 128, BSZ / 128), 256>>>(X, labels);
    rank_kernel<<<BSZ, 256>>>(labels);
    reduce_kernel<<<1, 256>>>(out);
}

// round 4
// speedup vs baseline: 1.1928x; 1.1928x over previous
#include <cuda_runtime.h>
#include <math_constants.h>

// Fixed dataset: batch_reprs [4096,128] f32, batch_labels [4096] i32
#define BSZ 4096
#define DIM 128
#define MARGIN 0.2f
#define NTILE 32                 // 4096/128 tiles per dim
#define NTRI  (NTILE*(NTILE+1)/2)  // 528 lower-triangle tiles

typedef unsigned long long u64;

// Scratch (static __device__ — no allocations allowed)
__device__ float g_sim[(size_t)BSZ * BSZ];   // 64 MB sim matrix
__device__ float g_sq[BSZ];
__device__ float g_partial[BSZ];

__device__ __forceinline__ u64 pack2(float x, float y) {
    u64 r; asm("mov.b64 %0, {%1,%2};" : "=l"(r) : "f"(x), "f"(y)); return r;
}
__device__ __forceinline__ void unpack2(u64 p, float &x, float &y) {
    asm("mov.b64 {%0,%1}, %2;" : "=f"(x), "=f"(y) : "l"(p));
}
__device__ __forceinline__ void fma2(u64 &d, u64 a, u64 b) {
    asm("fma.rn.f32x2 %0, %1, %2, %3;" : "=l"(d) : "l"(a), "l"(b), "l"(d));
}

// ---------------------------------------------------------------------------
// K1: row squared norms
// ---------------------------------------------------------------------------
__global__ void sq_kernel(const float* __restrict__ X) {
    int row = blockIdx.x * 8 + threadIdx.y;
    const float* x = X + row * DIM;
    float s = 0.f;
    for (int c = threadIdx.x; c < DIM; c += 32) {
        float v = x[c];
        s = fmaf(v, v, s);
    }
    #pragma unroll
    for (int o = 16; o; o >>= 1) s += __shfl_down_sync(0xffffffffu, s, o);
    if (threadIdx.x == 0) g_sq[row] = s;
}

// ---------------------------------------------------------------------------
// K2: symmetric sim matrix. Only lower-triangle 128x128 tiles computed
// (528 CTAs); off-diagonal tiles also write their transpose via an smem
// transpose so all gmem stores stay coalesced.
// Inner loop uses packed fma.rn.f32x2 (FFMA2) — 2x FFMA throughput on B300.
// ---------------------------------------------------------------------------
__global__ void __launch_bounds__(256, 2) sim_kernel(
    const float* __restrict__ X, const int* __restrict__ labels) {
    __shared__ float SM[64 * 132];          // GEMM: As=SM[0:32*132), Bs=SM[32*132:)
    float (*As)[132] = (float(*)[132])SM;
    float (*Bs)[132] = (float(*)[132])(SM + 32 * 132);

    // decode lower-triangle tile index
    int l = blockIdx.x;
    int bi = (int)((sqrtf(8.0f * (float)l + 1.0f) - 1.0f) * 0.5f);
    while ((bi + 1) * (bi + 2) / 2 <= l) bi++;
    while (bi * (bi + 1) / 2 > l) bi--;
    int bj = l - bi * (bi + 1) / 2;

    const int tileR = bi * 128;
    const int tileC = bj * 128;
    const int tid = threadIdx.x;
    const int tx = tid & 15;
    const int ty = tid >> 4;

    u64 acc2[8][4];
    #pragma unroll
    for (int i = 0; i < 8; i++)
        #pragma unroll
        for (int jp = 0; jp < 4; jp++) acc2[i][jp] = 0ull;

    for (int kk = 0; kk < DIM; kk += 32) {
        #pragma unroll
        for (int e = tid; e < 128 * 32; e += 256) {
            int r = e >> 5, c = e & 31;
            As[c][r] = X[(tileR + r) * DIM + kk + c];
            Bs[c][r] = X[(tileC + r) * DIM + kk + c];
        }
        __syncthreads();
        #pragma unroll
        for (int k = 0; k < 32; k++) {
            float4 a0 = *(const float4*)&As[k][ty * 8];
            float4 a1 = *(const float4*)&As[k][ty * 8 + 4];
            longlong2 bb0 = *(const longlong2*)&Bs[k][tx * 8];
            longlong2 bb1 = *(const longlong2*)&Bs[k][tx * 8 + 4];
            u64 b2[4] = {(u64)bb0.x, (u64)bb0.y, (u64)bb1.x, (u64)bb1.y};
            float a[8] = {a0.x, a0.y, a0.z, a0.w, a1.x, a1.y, a1.z, a1.w};
            u64 ad[8];
            #pragma unroll
            for (int i = 0; i < 8; i++) ad[i] = pack2(a[i], a[i]);
            #pragma unroll
            for (int i = 0; i < 8; i++)
                #pragma unroll
                for (int jp = 0; jp < 4; jp++)
                    fma2(acc2[i][jp], ad[i], b2[jp]);
        }
        __syncthreads();
    }

    // epilogue: convert acc -> sim values
    int   Lc[8]; float sqc[8];
    int   Lr[8]; float sqr[8];
    #pragma unroll
    for (int j = 0; j < 8; j++) {
        int c = tileC + tx * 8 + j;
        Lc[j]  = __ldg(&labels[c]);
        sqc[j] = __ldg(&g_sq[c]);
    }
    #pragma unroll
    for (int i = 0; i < 8; i++) {
        int r = tileR + ty * 8 + i;
        Lr[i]  = __ldg(&labels[r]);
        sqr[i] = __ldg(&g_sq[r]);
    }

    float o[8][8];
    #pragma unroll
    for (int i = 0; i < 8; i++) {
        #pragma unroll
        for (int jp = 0; jp < 4; jp++) {
            float d0, d1;
            unpack2(acc2[i][jp], d0, d1);
            float e0 = fmaxf(sqr[i] + sqc[2*jp]   - 2.0f * d0, 0.0f);
            float e1 = fmaxf(sqr[i] + sqc[2*jp+1] - 2.0f * d1, 0.0f);
            o[i][2*jp]   = -sqrtf(e0) + ((Lc[2*jp]   != Lr[i]) ? MARGIN : 0.0f);
            o[i][2*jp+1] = -sqrtf(e1) + ((Lc[2*jp+1] != Lr[i]) ? MARGIN : 0.0f);
        }
    }

    // direct store (R,C) tile — coalesced float4
    #pragma unroll
    for (int i = 0; i < 8; i++) {
        float* dst = &g_sim[(size_t)(tileR + ty * 8 + i) * BSZ + tileC + tx * 8];
        *(float4*)(dst)     = make_float4(o[i][0], o[i][1], o[i][2], o[i][3]);
        *(float4*)(dst + 4) = make_float4(o[i][4], o[i][5], o[i][6], o[i][7]);
    }

    // transposed store (C,R) tile via smem transpose, 2 chunks of 64 cols
    if (bi != bj) {
        const int ib = ty * 8;   // this thread's i-range base
        #pragma unroll
        for (int chunk = 0; chunk < 2; chunk++) {
            __syncthreads();     // SM free (GEMM done / prev chunk read done)
            if ((tx >> 3) == chunk) {
                int txl = tx & 7;
                #pragma unroll
                for (int jj = 0; jj < 8; jj++) {
                    int jc = txl * 8 + jj;              // 0..63 within chunk
                    int rot = ((((jc >> 3) ^ jc) & 7) << 4);
                    int w0 = jc * 132 + ((ib + rot) & 127);
                    *(float4*)&SM[w0]     = make_float4(o[0][jj], o[1][jj], o[2][jj], o[3][jj]);
                    *(float4*)&SM[w0 + 4] = make_float4(o[4][jj], o[5][jj], o[6][jj], o[7][jj]);
                }
            }
            __syncthreads();
            // read transposed rows, store coalesced: 64 rows x 128 floats
            int jl = tid >> 2;          // 0..63 row within chunk
            int lg = tid & 3;           // 4 threads per row
            int rot = ((((jl >> 3) ^ jl) & 7) << 4);
            size_t rowbase = (size_t)(tileC + chunk * 64 + jl) * BSZ + tileR;
            #pragma unroll
            for (int m = 0; m < 8; m++) {
                int i = lg * 32 + m * 4;
                float4 v = *(const float4*)&SM[jl * 132 + ((i + rot) & 127)];
                *(float4*)&g_sim[rowbase + i] = v;
            }
        }
    }
}

// ---------------------------------------------------------------------------
// K3: per-row ranking + loss partial. One CTA (256 threads / 8 warps) per row.
// Warp-local top-k over 512-element slices + serial merge; threshold-based
// fp/fn classification; fn global ranks in parallel across warps.
// ---------------------------------------------------------------------------
#define MAXK 64
__global__ void __launch_bounds__(256) rank_kernel(const int* __restrict__ labels) {
    __shared__ float s_sim[BSZ];        // 16 KB
    __shared__ unsigned s_mask[BSZ / 32]; // positive bitmask, 512 B
    __shared__ int   s_pos[MAXK];
    __shared__ float s_cval[8 * MAXK];  // per-warp sorted candidates
    __shared__ int   s_cidx[8 * MAXK];
    __shared__ float s_tks[MAXK];
    __shared__ int   s_tki[MAXK];
    __shared__ int   s_fn[MAXK];
    __shared__ int   s_fnrank[MAXK];
    __shared__ int   s_k, s_nfn;
    __shared__ float s_fp;

    const int row = blockIdx.x;
    const int tid = threadIdx.x;
    const int wid = tid >> 5;
    const int lane = tid & 31;
    const float* srow = g_sim + (size_t)row * BSZ;
    const int L = __ldg(&labels[row]);

    // Phase 1: load sim row + build positive bitmask via ballots
    #pragma unroll
    for (int t = 0; t < BSZ / 256; t++) {
        int j = t * 256 + tid;
        s_sim[j] = srow[j];
        int lbl = __ldg(&labels[j]);
        unsigned m = __ballot_sync(0xffffffffu, lbl == L);
        if (lane == 0) s_mask[t * 8 + wid] = m;
    }
    __syncthreads();

    // Phase 2a: tid0 builds ordered positive list; 2b: warps cache slices
    if (tid == 0) {
        int cnt = 0;
        for (int w = 0; w < BSZ / 32; w++) {
            unsigned m = s_mask[w];
            while (m && cnt < MAXK) {
                int b = __ffs(m) - 1;
                m &= m - 1;
                s_pos[cnt++] = w * 32 + b;
            }
        }
        s_k = cnt;
    }
    float v[16];
    #pragma unroll
    for (int i = 0; i < 16; i++) v[i] = s_sim[wid * 512 + i * 32 + lane];
    __syncthreads();

    const int k = s_k;

    // Phase 3: warp-local top-k with removal (each slice has 512 >= k elems)
    for (int r = 0; r < k; r++) {
        float bs = -CUDART_INF_F;
        int   bi = 0x7fffffff;
        #pragma unroll
        for (int i = 0; i < 16; i++) {
            float s = v[i];
            int j = wid * 512 + i * 32 + lane;
            if (s > bs || (s == bs && j < bi)) { bs = s; bi = j; }
        }
        #pragma unroll
        for (int o = 16; o; o >>= 1) {
            float os = __shfl_down_sync(0xffffffffu, bs, o);
            int   oi = __shfl_down_sync(0xffffffffu, bi, o);
            if (os > bs || (os == bs && oi < bi)) { bs = os; bi = oi; }
        }
        bs = __shfl_sync(0xffffffffu, bs, 0);
        bi = __shfl_sync(0xffffffffu, bi, 0);
        if (lane == 0) { s_cval[wid * MAXK + r] = bs; s_cidx[wid * MAXK + r] = bi; }
        #pragma unroll
        for (int i = 0; i < 16; i++)
            if (bi == wid * 512 + i * 32 + lane) v[i] = -CUDART_INF_F;
    }
    __syncthreads();

    // Phase 4: merge 8 sorted lists, compute fp_term + fn list (tid0)
    if (tid == 0) {
        int ptr[8] = {0, 0, 0, 0, 0, 0, 0, 0};
        for (int r = 0; r < k; r++) {
            float bs = -CUDART_INF_F; int bi = 0x7fffffff; int bw = 0;
            #pragma unroll
            for (int w = 0; w < 8; w++) {
                if (ptr[w] < k) {
                    float s = s_cval[w * MAXK + ptr[w]];
                    int   j = s_cidx[w * MAXK + ptr[w]];
                    if (s > bs || (s == bs && j < bi)) { bs = s; bi = j; bw = w; }
                }
            }
            ptr[bw]++;
            s_tks[r] = bs; s_tki[r] = bi;
        }
        float thr_s = s_tks[k - 1];
        int   thr_i = s_tki[k - 1];
        float kf = (float)k;
        float fp = 0.0f;
        for (int r = 0; r < k; r++) {
            int j = s_tki[r];
            bool pos = (s_mask[j >> 5] >> (j & 31)) & 1u;
            if (!pos) {
                float rank = (float)(r + 1);
                fp += s_tks[r] * (0.5f + (kf - rank + 1.0f) / kf * 0.5f);
            }
        }
        int nfn = 0;
        for (int p = 0; p < k; p++) {
            int j = s_pos[p];
            float s = s_sim[j];
            if (s < thr_s || (s == thr_s && j > thr_i)) s_fn[nfn++] = j;
        }
        s_fp = fp;
        s_nfn = nfn;
    }
    __syncthreads();

    // Phase 5: global rank of each fn positive, parallel across warps
    const int nfn = s_nfn;
    for (int q = wid; q < nfn; q += 8) {
        int j = s_fn[q];
        float s = s_sim[j];
        int c = 0;
        #pragma unroll 8
        for (int m = lane; m < BSZ; m += 32) {
            float vv = s_sim[m];
            c += (vv > s) ? 1 : 0;
            c += (vv == s && m < j) ? 1 : 0;
        }
        #pragma unroll
        for (int o = 16; o; o >>= 1) c += __shfl_down_sync(0xffffffffu, c, o);
        if (lane == 0) s_fnrank[q] = c + 1;
    }
    __syncthreads();

    // Phase 6: final accumulate (tid0)
    if (tid == 0) {
        float kf = (float)k;
        float nk = (float)BSZ - kf;
        float fn_term = 0.0f;
        for (int q = 0; q < nfn; q++) {
            int j = s_fn[q];
            float rank = (float)s_fnrank[q];
            fn_term += s_sim[j] * (0.5f + (rank - kf) / nk * 0.5f);
        }
        g_partial[row] = s_fp - fn_term;
    }
}

// ---------------------------------------------------------------------------
// K4: deterministic fixed-order reduction of row partials
// ---------------------------------------------------------------------------
__global__ void reduce_kernel(float* __restrict__ out) {
    __shared__ float s[256];
    int tid = threadIdx.x;
    float a = 0.0f;
    #pragma unroll
    for (int i = 0; i < BSZ / 256; i++) a += g_partial[i * 256 + tid];
    s[tid] = a;
    __syncthreads();
    for (int o = 128; o; o >>= 1) {
        if (tid < o) s[tid] += s[tid + o];
        __syncthreads();
    }
    if (tid == 0) out[0] = s[0];
}

// ---------------------------------------------------------------------------
extern "C" void kernel_launch(void* const* d_in, const int* in_sizes, int n_in,
                              void* d_out, int out_size) {
    const float* X      = (const float*)d_in[0];   // batch_reprs [4096,128] f32
    const int*   labels = (const int*)d_in[1];     // batch_labels [4096] i32
    float* out = (float*)d_out;

    sq_kernel<<<BSZ / 8, dim3(32, 8)>>>(X);
    sim_kernel<<<NTRI, 256>>>(X, labels);
    rank_kernel<<<BSZ, 256>>>(labels);
    reduce_kernel<<<1, 256>>>(out);
}

// round 6
// speedup vs baseline: 1.3033x; 1.0926x over previous
#include <cuda_runtime.h>
#include <cuda_fp16.h>
#include <math_constants.h>
#include <cstdint>

// Fixed dataset: batch_reprs [4096,128] f32, batch_labels [4096] i32
#define BSZ 4096
#define DIM 128
#define MARGIN 0.2f
#define NTILE 32                   // 4096/128 tiles per dim
#define NTRI  (NTILE*(NTILE+1)/2)  // 528 lower-triangle tiles

// Scratch (static __device__ — no allocations allowed)
__device__ float g_sim[(size_t)BSZ * BSZ];   // 64 MB sim matrix
__device__ float g_sq[BSZ];
__device__ float g_partial[BSZ];
__device__ __half g_xh[(size_t)BSZ * DIM];   // hi fp16 limb
__device__ __half g_xl[(size_t)BSZ * DIM];   // lo fp16 limb

// smem layout (bytes) for sim kernel; half-tile rows padded to 136 halves (17 uint4)
#define T_BYTES (128 * 136 * 2)    // 34816
#define OFF_AH  0
#define OFF_AL  (T_BYTES)
#define OFF_BH  (2 * T_BYTES)
#define OFF_BL  (3 * T_BYTES)
#define OFF_SQR (4 * T_BYTES)              // 139264, 128 f32
#define OFF_SQC (OFF_SQR + 512)
#define OFF_LR  (OFF_SQC + 512)
#define OFF_LC  (OFF_LR + 512)
#define OFF_STG (OFF_LC + 512)             // 141312, stage 128x132 f32
#define SIM_SMEM (OFF_STG + 128 * 132 * 4) // 208896 B

__device__ __forceinline__ uint32_t smem_u32(const void* p) {
    uint32_t a;
    asm("{ .reg .u64 t; cvta.to.shared.u64 t, %1; cvt.u32.u64 %0, t; }" : "=r"(a) : "l"(p));
    return a;
}
__device__ __forceinline__ void ldsm4(uint32_t* r, uint32_t addr) {
    asm volatile("ldmatrix.sync.aligned.m8n8.x4.shared.b16 {%0,%1,%2,%3}, [%4];"
                 : "=r"(r[0]), "=r"(r[1]), "=r"(r[2]), "=r"(r[3]) : "r"(addr));
}
__device__ __forceinline__ void mma16816(float* c, const uint32_t* a, const uint32_t* b) {
    asm volatile(
        "mma.sync.aligned.m16n8k16.row.col.f32.f16.f16.f32 "
        "{%0,%1,%2,%3}, {%4,%5,%6,%7}, {%8,%9}, {%0,%1,%2,%3};"
        : "+f"(c[0]), "+f"(c[1]), "+f"(c[2]), "+f"(c[3])
        : "r"(a[0]), "r"(a[1]), "r"(a[2]), "r"(a[3]), "r"(b[0]), "r"(b[1]));
}

// ---------------------------------------------------------------------------
// K1: prep — row squared norms + fp16 hi/lo limb split
// ---------------------------------------------------------------------------
__global__ void prep_kernel(const float* __restrict__ X) {
    int row = blockIdx.x * 8 + threadIdx.y;
    const float* x = X + row * DIM;
    float s = 0.f;
    for (int c = threadIdx.x; c < DIM; c += 32) {
        float v = x[c];
        s = fmaf(v, v, s);
        __half h = __float2half_rn(v);
        float r = v - __half2float(h);
        g_xh[row * DIM + c] = h;
        g_xl[row * DIM + c] = __float2half_rn(r);
    }
    #pragma unroll
    for (int o = 16; o; o >>= 1) s += __shfl_down_sync(0xffffffffu, s, o);
    if (threadIdx.x == 0) g_sq[row] = s;
}

// ---------------------------------------------------------------------------
// K2: sim via mma.sync fp16 split GEMM. 528 triangle tiles; 256 thr (8 warps);
// warp tile 32x64; dot = hi*hi + lo*hi + hi*lo, fp32 accumulate.
// ---------------------------------------------------------------------------
__global__ void __launch_bounds__(256, 1) sim_mma_kernel(const int* __restrict__ labels) {
    extern __shared__ char sm[];
    const uint32_t smb = smem_u32(sm);
    const int tid = threadIdx.x;

    // decode lower-triangle tile index
    int l = blockIdx.x;
    int bi = (int)((sqrtf(8.0f * (float)l + 1.0f) - 1.0f) * 0.5f);
    while ((bi + 1) * (bi + 2) / 2 <= l) bi++;
    while (bi * (bi + 1) / 2 > l) bi--;
    int bj = l - bi * (bi + 1) / 2;
    const int tileR = bi * 128;
    const int tileC = bj * 128;

    // ---- load 4 limb tiles (row-major, 136-half padded) + sq/labels ----
    {
        const uint4* gAH = (const uint4*)(g_xh + (size_t)tileR * DIM);
        const uint4* gAL = (const uint4*)(g_xl + (size_t)tileR * DIM);
        const uint4* gBH = (const uint4*)(g_xh + (size_t)tileC * DIM);
        const uint4* gBL = (const uint4*)(g_xl + (size_t)tileC * DIM);
        uint4* sAH = (uint4*)(sm + OFF_AH);
        uint4* sAL = (uint4*)(sm + OFF_AL);
        uint4* sBH = (uint4*)(sm + OFF_BH);
        uint4* sBL = (uint4*)(sm + OFF_BL);
        #pragma unroll
        for (int i = 0; i < 8; i++) {
            int id = i * 256 + tid;          // 2048 16B-chunks per tile
            int row = id >> 4, c = id & 15;  // 16 chunks per 128-half row
            int so = row * 17 + c;           // smem row = 17 uint4 (136 halves)
            int gi = row * 16 + c;
            sAH[so] = gAH[gi];
            sAL[so] = gAL[gi];
            sBH[so] = gBH[gi];
            sBL[so] = gBL[gi];
        }
        if (tid < 128) {
            ((float*)(sm + OFF_SQR))[tid] = g_sq[tileR + tid];
            ((float*)(sm + OFF_SQC))[tid] = g_sq[tileC + tid];
            ((int*)(sm + OFF_LR))[tid] = labels[tileR + tid];
            ((int*)(sm + OFF_LC))[tid] = labels[tileC + tid];
        }
    }
    __syncthreads();

    // ---- MMA mainloop ----
    const int w = tid >> 5, ln = tid & 31;
    const int wm = w >> 1, wn = w & 1;
    const int R0 = wm * 32, C0 = wn * 64;

    float acc[2][8][4];
    #pragma unroll
    for (int mt = 0; mt < 2; mt++)
        #pragma unroll
        for (int t = 0; t < 8; t++)
            #pragma unroll
            for (int e = 0; e < 4; e++) acc[mt][t][e] = 0.f;

    // lane-dependent ldmatrix offsets (bytes)
    const uint32_t aoff = (uint32_t)(((R0 + (ln & 15)) * 136 + (((ln >> 4) & 1) << 3)) * 2);
    const uint32_t boff = (uint32_t)(((C0 + (ln & 7) + (((ln >> 4) & 1) << 3)) * 136
                                      + (((ln >> 3) & 1) << 3)) * 2);
    const uint32_t MT_STRIDE = 16 * 136 * 2;  // next m16 tile
    const uint32_t NG_STRIDE = 16 * 136 * 2;  // next n16 group

    const uint32_t aBase[3] = {smb + OFF_AH, smb + OFF_AH, smb + OFF_AL};
    const uint32_t bBase[3] = {smb + OFF_BH, smb + OFF_BL, smb + OFF_BH};

    #pragma unroll
    for (int p = 0; p < 3; p++) {
        const uint32_t aB = aBase[p] + aoff;
        const uint32_t bB = bBase[p] + boff;
        #pragma unroll
        for (int ks = 0; ks < 8; ks++) {
            const uint32_t kByte = (uint32_t)ks * 32;   // 16 halves
            uint32_t a[2][4];
            ldsm4(a[0], aB + kByte);
            ldsm4(a[1], aB + MT_STRIDE + kByte);
            uint32_t b[8][2];
            #pragma unroll
            for (int g = 0; g < 4; g++) {
                uint32_t r4[4];
                ldsm4(r4, bB + g * NG_STRIDE + kByte);
                b[2 * g][0] = r4[0]; b[2 * g][1] = r4[1];
                b[2 * g + 1][0] = r4[2]; b[2 * g + 1][1] = r4[3];
            }
            #pragma unroll
            for (int mt = 0; mt < 2; mt++)
                #pragma unroll
                for (int t = 0; t < 8; t++)
                    mma16816(acc[mt][t], a[mt], b[t]);
        }
    }

    // ---- epilogue: dot -> sim, write to stage ----
    const float* sqR = (const float*)(sm + OFF_SQR);
    const float* sqC = (const float*)(sm + OFF_SQC);
    const int* lR = (const int*)(sm + OFF_LR);
    const int* lC = (const int*)(sm + OFF_LC);
    float* stage = (float*)(sm + OFF_STG);

    const int l4 = ln >> 2, l2 = (ln & 3) * 2;
    #pragma unroll
    for (int mt = 0; mt < 2; mt++) {
        int rlo = R0 + mt * 16 + l4;
        int rhi = rlo + 8;
        float sql = sqR[rlo], sqh = sqR[rhi];
        int Ll = lR[rlo], Lh = lR[rhi];
        #pragma unroll
        for (int t = 0; t < 8; t++) {
            int c0 = C0 + t * 8 + l2;
            float q0 = sqC[c0], q1 = sqC[c0 + 1];
            int L0 = lC[c0], L1 = lC[c0 + 1];
            float d;
            d = fmaxf(sql + q0 - 2.0f * acc[mt][t][0], 0.f);
            stage[rlo * 132 + c0]     = -sqrtf(d) + ((L0 != Ll) ? MARGIN : 0.f);
            d = fmaxf(sql + q1 - 2.0f * acc[mt][t][1], 0.f);
            stage[rlo * 132 + c0 + 1] = -sqrtf(d) + ((L1 != Ll) ? MARGIN : 0.f);
            d = fmaxf(sqh + q0 - 2.0f * acc[mt][t][2], 0.f);
            stage[rhi * 132 + c0]     = -sqrtf(d) + ((L0 != Lh) ? MARGIN : 0.f);
            d = fmaxf(sqh + q1 - 2.0f * acc[mt][t][3], 0.f);
            stage[rhi * 132 + c0 + 1] = -sqrtf(d) + ((L1 != Lh) ? MARGIN : 0.f);
        }
    }
    __syncthreads();

    // ---- copy-out: direct tile (coalesced float4) ----
    {
        int row = tid >> 1, part = tid & 1;
        const float* sp = &stage[row * 132 + part * 64];
        float* dst = &g_sim[(size_t)(tileR + row) * BSZ + tileC + part * 64];
        #pragma unroll
        for (int q = 0; q < 16; q++)
            *(float4*)(dst + q * 4) = *(const float4*)(sp + q * 4);
    }
    // ---- transposed tile for off-diagonal (gather columns, coalesced stores) ----
    if (bi != bj) {
        int c = tid >> 1, part = tid & 1;
        int rbase = part * 64;
        float* dst = &g_sim[(size_t)(tileC + c) * BSZ + tileR + rbase];
        #pragma unroll
        for (int q = 0; q < 16; q++) {
            float4 v;
            v.x = stage[(rbase + q * 4 + 0) * 132 + c];
            v.y = stage[(rbase + q * 4 + 1) * 132 + c];
            v.z = stage[(rbase + q * 4 + 2) * 132 + c];
            v.w = stage[(rbase + q * 4 + 3) * 132 + c];
            *(float4*)(dst + q * 4) = v;
        }
    }
}

// ---------------------------------------------------------------------------
// K3: per-row ranking + loss partial (verified in rounds 2/4)
// ---------------------------------------------------------------------------
#define MAXK 64
__global__ void __launch_bounds__(256) rank_kernel(const int* __restrict__ labels) {
    __shared__ float s_sim[BSZ];
    __shared__ unsigned s_mask[BSZ / 32];
    __shared__ int   s_pos[MAXK];
    __shared__ float s_cval[8 * MAXK];
    __shared__ int   s_cidx[8 * MAXK];
    __shared__ float s_tks[MAXK];
    __shared__ int   s_tki[MAXK];
    __shared__ int   s_fn[MAXK];
    __shared__ int   s_fnrank[MAXK];
    __shared__ int   s_k, s_nfn;
    __shared__ float s_fp;

    const int row = blockIdx.x;
    const int tid = threadIdx.x;
    const int wid = tid >> 5;
    const int lane = tid & 31;
    const float* srow = g_sim + (size_t)row * BSZ;
    const int L = __ldg(&labels[row]);

    #pragma unroll
    for (int t = 0; t < BSZ / 256; t++) {
        int j = t * 256 + tid;
        s_sim[j] = srow[j];
        int lbl = __ldg(&labels[j]);
        unsigned m = __ballot_sync(0xffffffffu, lbl == L);
        if (lane == 0) s_mask[t * 8 + wid] = m;
    }
    __syncthreads();

    if (tid == 0) {
        int cnt = 0;
        for (int w = 0; w < BSZ / 32; w++) {
            unsigned m = s_mask[w];
            while (m && cnt < MAXK) {
                int b = __ffs(m) - 1;
                m &= m - 1;
                s_pos[cnt++] = w * 32 + b;
            }
        }
        s_k = cnt;
    }
    float v[16];
    #pragma unroll
    for (int i = 0; i < 16; i++) v[i] = s_sim[wid * 512 + i * 32 + lane];
    __syncthreads();

    const int k = s_k;

    for (int r = 0; r < k; r++) {
        float bs = -CUDART_INF_F;
        int   bi = 0x7fffffff;
        #pragma unroll
        for (int i = 0; i < 16; i++) {
            float s = v[i];
            int j = wid * 512 + i * 32 + lane;
            if (s > bs || (s == bs && j < bi)) { bs = s; bi = j; }
        }
        #pragma unroll
        for (int o = 16; o; o >>= 1) {
            float os = __shfl_down_sync(0xffffffffu, bs, o);
            int   oi = __shfl_down_sync(0xffffffffu, bi, o);
            if (os > bs || (os == bs && oi < bi)) { bs = os; bi = oi; }
        }
        bs = __shfl_sync(0xffffffffu, bs, 0);
        bi = __shfl_sync(0xffffffffu, bi, 0);
        if (lane == 0) { s_cval[wid * MAXK + r] = bs; s_cidx[wid * MAXK + r] = bi; }
        #pragma unroll
        for (int i = 0; i < 16; i++)
            if (bi == wid * 512 + i * 32 + lane) v[i] = -CUDART_INF_F;
    }
    __syncthreads();

    if (tid == 0) {
        int ptr[8] = {0, 0, 0, 0, 0, 0, 0, 0};
        for (int r = 0; r < k; r++) {
            float bs = -CUDART_INF_F; int bi = 0x7fffffff; int bw = 0;
            #pragma unroll
            for (int w = 0; w < 8; w++) {
                if (ptr[w] < k) {
                    float s = s_cval[w * MAXK + ptr[w]];
                    int   j = s_cidx[w * MAXK + ptr[w]];
                    if (s > bs || (s == bs && j < bi)) { bs = s; bi = j; bw = w; }
                }
            }
            ptr[bw]++;
            s_tks[r] = bs; s_tki[r] = bi;
        }
        float thr_s = s_tks[k - 1];
        int   thr_i = s_tki[k - 1];
        float kf = (float)k;
        float fp = 0.0f;
        for (int r = 0; r < k; r++) {
            int j = s_tki[r];
            bool pos = (s_mask[j >> 5] >> (j & 31)) & 1u;
            if (!pos) {
                float rank = (float)(r + 1);
                fp += s_tks[r] * (0.5f + (kf - rank + 1.0f) / kf * 0.5f);
            }
        }
        int nfn = 0;
        for (int p = 0; p < k; p++) {
            int j = s_pos[p];
            float s = s_sim[j];
            if (s < thr_s || (s == thr_s && j > thr_i)) s_fn[nfn++] = j;
        }
        s_fp = fp;
        s_nfn = nfn;
    }
    __syncthreads();

    const int nfn = s_nfn;
    for (int q = wid; q < nfn; q += 8) {
        int j = s_fn[q];
        float s = s_sim[j];
        int c = 0;
        #pragma unroll 8
        for (int m = lane; m < BSZ; m += 32) {
            float vv = s_sim[m];
            c += (vv > s) ? 1 : 0;
            c += (vv == s && m < j) ? 1 : 0;
        }
        #pragma unroll
        for (int o = 16; o; o >>= 1) c += __shfl_down_sync(0xffffffffu, c, o);
        if (lane == 0) s_fnrank[q] = c + 1;
    }
    __syncthreads();

    if (tid == 0) {
        float kf = (float)k;
        float nk = (float)BSZ - kf;
        float fn_term = 0.0f;
        for (int q = 0; q < nfn; q++) {
            int j = s_fn[q];
            float rank = (float)s_fnrank[q];
            fn_term += s_sim[j] * (0.5f + (rank - kf) / nk * 0.5f);
        }
        g_partial[row] = s_fp - fn_term;
    }
}

// ---------------------------------------------------------------------------
// K4: deterministic fixed-order reduction
// ---------------------------------------------------------------------------
__global__ void reduce_kernel(float* __restrict__ out) {
    __shared__ float s[256];
    int tid = threadIdx.x;
    float a = 0.0f;
    #pragma unroll
    for (int i = 0; i < BSZ / 256; i++) a += g_partial[i * 256 + tid];
    s[tid] = a;
    __syncthreads();
    for (int o = 128; o; o >>= 1) {
        if (tid < o) s[tid] += s[tid + o];
        __syncthreads();
    }
    if (tid == 0) out[0] = s[0];
}

// ---------------------------------------------------------------------------
extern "C" void kernel_launch(void* const* d_in, const int* in_sizes, int n_in,
                              void* d_out, int out_size) {
    const float* X      = (const float*)d_in[0];   // batch_reprs [4096,128] f32
    const int*   labels = (const int*)d_in[1];     // batch_labels [4096] i32
    float* out = (float*)d_out;

    cudaFuncSetAttribute(sim_mma_kernel, cudaFuncAttributeMaxDynamicSharedMemorySize, SIM_SMEM);

    prep_kernel<<<BSZ / 8, dim3(32, 8)>>>(X);
    sim_mma_kernel<<<NTRI, 256, SIM_SMEM>>>(labels);
    rank_kernel<<<BSZ, 256>>>(labels);
    reduce_kernel<<<1, 256>>>(out);
}

// round 8
// speedup vs baseline: 1.3392x; 1.0275x over previous
#include <cuda_runtime.h>
#include <cuda_fp16.h>
#include <math_constants.h>
#include <cstdint>

// Fixed dataset: batch_reprs [4096,128] f32, batch_labels [4096] i32
#define BSZ 4096
#define DIM 128
#define MARGIN 0.2f
#define NTILE 32                   // 4096/128 tiles per dim
#define NTRI  (NTILE*(NTILE+1)/2)  // 528 lower-triangle tiles

// Scratch (static __device__ — no allocations allowed)
__device__ float g_sim[(size_t)BSZ * BSZ];   // 64 MB sim matrix
__device__ float g_sq[BSZ];
__device__ float g_partial[BSZ];
__device__ __half g_xh[(size_t)BSZ * DIM];   // hi fp16 limb
__device__ __half g_xl[(size_t)BSZ * DIM];   // lo fp16 limb

// smem layout (bytes) for sim kernel; half-tile rows padded to 136 halves (17 uint4)
#define T_BYTES (128 * 136 * 2)    // 34816
#define OFF_AH  0
#define OFF_AL  (T_BYTES)
#define OFF_BH  (2 * T_BYTES)
#define OFF_BL  (3 * T_BYTES)
#define OFF_SQR (4 * T_BYTES)              // 139264, 128 f32
#define OFF_SQC (OFF_SQR + 512)
#define OFF_LR  (OFF_SQC + 512)
#define OFF_LC  (OFF_LR + 512)
#define OFF_STG (OFF_LC + 512)             // stage 128x132 f32
#define SIM_SMEM (OFF_STG + 128 * 132 * 4) // 208896 B

__device__ __forceinline__ uint32_t smem_u32(const void* p) {
    uint32_t a;
    asm("{ .reg .u64 t; cvta.to.shared.u64 t, %1; cvt.u32.u64 %0, t; }" : "=r"(a) : "l"(p));
    return a;
}
__device__ __forceinline__ void ldsm4(uint32_t* r, uint32_t addr) {
    asm volatile("ldmatrix.sync.aligned.m8n8.x4.shared.b16 {%0,%1,%2,%3}, [%4];"
                 : "=r"(r[0]), "=r"(r[1]), "=r"(r[2]), "=r"(r[3]) : "r"(addr));
}
__device__ __forceinline__ void mma16816(float* c, const uint32_t* a, const uint32_t* b) {
    asm volatile(
        "mma.sync.aligned.m16n8k16.row.col.f32.f16.f16.f32 "
        "{%0,%1,%2,%3}, {%4,%5,%6,%7}, {%8,%9}, {%0,%1,%2,%3};"
        : "+f"(c[0]), "+f"(c[1]), "+f"(c[2]), "+f"(c[3])
        : "r"(a[0]), "r"(a[1]), "r"(a[2]), "r"(a[3]), "r"(b[0]), "r"(b[1]));
}

// ---------------------------------------------------------------------------
// K1: prep — row squared norms + fp16 hi/lo limb split
// ---------------------------------------------------------------------------
__global__ void prep_kernel(const float* __restrict__ X) {
    int row = blockIdx.x * 8 + threadIdx.y;
    const float* x = X + row * DIM;
    float s = 0.f;
    for (int c = threadIdx.x; c < DIM; c += 32) {
        float v = x[c];
        s = fmaf(v, v, s);
        __half h = __float2half_rn(v);
        float r = v - __half2float(h);
        g_xh[row * DIM + c] = h;
        g_xl[row * DIM + c] = __float2half_rn(r);
    }
    #pragma unroll
    for (int o = 16; o; o >>= 1) s += __shfl_down_sync(0xffffffffu, s, o);
    if (threadIdx.x == 0) g_sq[row] = s;
}

// ---------------------------------------------------------------------------
// K2: sim via mma.sync fp16 split GEMM (unchanged from round 6 — verified)
// ---------------------------------------------------------------------------
__global__ void __launch_bounds__(256, 1) sim_mma_kernel(const int* __restrict__ labels) {
    extern __shared__ char sm[];
    const uint32_t smb = smem_u32(sm);
    const int tid = threadIdx.x;

    int l = blockIdx.x;
    int bi = (int)((sqrtf(8.0f * (float)l + 1.0f) - 1.0f) * 0.5f);
    while ((bi + 1) * (bi + 2) / 2 <= l) bi++;
    while (bi * (bi + 1) / 2 > l) bi--;
    int bj = l - bi * (bi + 1) / 2;
    const int tileR = bi * 128;
    const int tileC = bj * 128;

    {
        const uint4* gAH = (const uint4*)(g_xh + (size_t)tileR * DIM);
        const uint4* gAL = (const uint4*)(g_xl + (size_t)tileR * DIM);
        const uint4* gBH = (const uint4*)(g_xh + (size_t)tileC * DIM);
        const uint4* gBL = (const uint4*)(g_xl + (size_t)tileC * DIM);
        uint4* sAH = (uint4*)(sm + OFF_AH);
        uint4* sAL = (uint4*)(sm + OFF_AL);
        uint4* sBH = (uint4*)(sm + OFF_BH);
        uint4* sBL = (uint4*)(sm + OFF_BL);
        #pragma unroll
        for (int i = 0; i < 8; i++) {
            int id = i * 256 + tid;
            int row = id >> 4, c = id & 15;
            int so = row * 17 + c;
            int gi = row * 16 + c;
            sAH[so] = gAH[gi];
            sAL[so] = gAL[gi];
            sBH[so] = gBH[gi];
            sBL[so] = gBL[gi];
        }
        if (tid < 128) {
            ((float*)(sm + OFF_SQR))[tid] = g_sq[tileR + tid];
            ((float*)(sm + OFF_SQC))[tid] = g_sq[tileC + tid];
            ((int*)(sm + OFF_LR))[tid] = labels[tileR + tid];
            ((int*)(sm + OFF_LC))[tid] = labels[tileC + tid];
        }
    }
    __syncthreads();

    const int w = tid >> 5, ln = tid & 31;
    const int wm = w >> 1, wn = w & 1;
    const int R0 = wm * 32, C0 = wn * 64;

    float acc[2][8][4];
    #pragma unroll
    for (int mt = 0; mt < 2; mt++)
        #pragma unroll
        for (int t = 0; t < 8; t++)
            #pragma unroll
            for (int e = 0; e < 4; e++) acc[mt][t][e] = 0.f;

    const uint32_t aoff = (uint32_t)(((R0 + (ln & 15)) * 136 + (((ln >> 4) & 1) << 3)) * 2);
    const uint32_t boff = (uint32_t)(((C0 + (ln & 7) + (((ln >> 4) & 1) << 3)) * 136
                                      + (((ln >> 3) & 1) << 3)) * 2);
    const uint32_t MT_STRIDE = 16 * 136 * 2;
    const uint32_t NG_STRIDE = 16 * 136 * 2;

    const uint32_t aBase[3] = {smb + OFF_AH, smb + OFF_AH, smb + OFF_AL};
    const uint32_t bBase[3] = {smb + OFF_BH, smb + OFF_BL, smb + OFF_BH};

    #pragma unroll
    for (int p = 0; p < 3; p++) {
        const uint32_t aB = aBase[p] + aoff;
        const uint32_t bB = bBase[p] + boff;
        #pragma unroll
        for (int ks = 0; ks < 8; ks++) {
            const uint32_t kByte = (uint32_t)ks * 32;
            uint32_t a[2][4];
            ldsm4(a[0], aB + kByte);
            ldsm4(a[1], aB + MT_STRIDE + kByte);
            uint32_t b[8][2];
            #pragma unroll
            for (int g = 0; g < 4; g++) {
                uint32_t r4[4];
                ldsm4(r4, bB + g * NG_STRIDE + kByte);
                b[2 * g][0] = r4[0]; b[2 * g][1] = r4[1];
                b[2 * g + 1][0] = r4[2]; b[2 * g + 1][1] = r4[3];
            }
            #pragma unroll
            for (int mt = 0; mt < 2; mt++)
                #pragma unroll
                for (int t = 0; t < 8; t++)
                    mma16816(acc[mt][t], a[mt], b[t]);
        }
    }

    const float* sqR = (const float*)(sm + OFF_SQR);
    const float* sqC = (const float*)(sm + OFF_SQC);
    const int* lR = (const int*)(sm + OFF_LR);
    const int* lC = (const int*)(sm + OFF_LC);
    float* stage = (float*)(sm + OFF_STG);

    const int l4 = ln >> 2, l2 = (ln & 3) * 2;
    #pragma unroll
    for (int mt = 0; mt < 2; mt++) {
        int rlo = R0 + mt * 16 + l4;
        int rhi = rlo + 8;
        float sql = sqR[rlo], sqh = sqR[rhi];
        int Ll = lR[rlo], Lh = lR[rhi];
        #pragma unroll
        for (int t = 0; t < 8; t++) {
            int c0 = C0 + t * 8 + l2;
            float q0 = sqC[c0], q1 = sqC[c0 + 1];
            int L0 = lC[c0], L1 = lC[c0 + 1];
            float d;
            d = fmaxf(sql + q0 - 2.0f * acc[mt][t][0], 0.f);
            stage[rlo * 132 + c0]     = -sqrtf(d) + ((L0 != Ll) ? MARGIN : 0.f);
            d = fmaxf(sql + q1 - 2.0f * acc[mt][t][1], 0.f);
            stage[rlo * 132 + c0 + 1] = -sqrtf(d) + ((L1 != Ll) ? MARGIN : 0.f);
            d = fmaxf(sqh + q0 - 2.0f * acc[mt][t][2], 0.f);
            stage[rhi * 132 + c0]     = -sqrtf(d) + ((L0 != Lh) ? MARGIN : 0.f);
            d = fmaxf(sqh + q1 - 2.0f * acc[mt][t][3], 0.f);
            stage[rhi * 132 + c0 + 1] = -sqrtf(d) + ((L1 != Lh) ? MARGIN : 0.f);
        }
    }
    __syncthreads();

    {
        int row = tid >> 1, part = tid & 1;
        const float* sp = &stage[row * 132 + part * 64];
        float* dst = &g_sim[(size_t)(tileR + row) * BSZ + tileC + part * 64];
        #pragma unroll
        for (int q = 0; q < 16; q++)
            *(float4*)(dst + q * 4) = *(const float4*)(sp + q * 4);
    }
    if (bi != bj) {
        int c = tid >> 1, part = tid & 1;
        int rbase = part * 64;
        float* dst = &g_sim[(size_t)(tileC + c) * BSZ + tileR + rbase];
        #pragma unroll
        for (int q = 0; q < 16; q++) {
            float4 v;
            v.x = stage[(rbase + q * 4 + 0) * 132 + c];
            v.y = stage[(rbase + q * 4 + 1) * 132 + c];
            v.z = stage[(rbase + q * 4 + 2) * 132 + c];
            v.w = stage[(rbase + q * 4 + 3) * 132 + c];
            *(float4*)(dst + q * 4) = v;
        }
    }
}

// ---------------------------------------------------------------------------
// K3: rank via histogram selection. One CTA (256 thr) per row.
// k-th largest found by 2048-bin histogram + suffix scan + tiny in-bin
// iterative max; fp/fn classified by threshold; ranks by counting.
// ---------------------------------------------------------------------------
#define NB   2048
#define MAXC 256
__global__ void __launch_bounds__(256) rank_kernel(const int* __restrict__ labels) {
    __shared__ float s_sim[BSZ];          // 16 KB
    __shared__ unsigned s_mask[BSZ / 32]; // 512 B
    __shared__ int   s_hist[NB];          // 8 KB
    __shared__ int   sS[256];             // 1 KB suffix-scan
    __shared__ float red_f[8];
    __shared__ int   red_i[8];
    __shared__ float s_mn, s_mx, s_invw;
    __shared__ int   s_k, s_nc, s_binB, s_above;
    __shared__ float s_ts;
    __shared__ int   s_ti;
    __shared__ int   s_cand[MAXC];
    __shared__ int   s_crank[MAXC];

    const int row = blockIdx.x;
    const int tid = threadIdx.x;
    const int wid = tid >> 5;
    const int lane = tid & 31;
    const float* srow = g_sim + (size_t)row * BSZ;
    const int L = __ldg(&labels[row]);

    if (tid == 0) { s_k = 0; s_nc = 0; }
    #pragma unroll
    for (int i = 0; i < NB / 256; i++) s_hist[tid + i * 256] = 0;
    __syncthreads();

    // Pass A: load + mask + min/max + k count
    float mn = CUDART_INF_F, mx = -CUDART_INF_F;
    int kc = 0;
    #pragma unroll
    for (int t = 0; t < BSZ / 256; t++) {
        int j = t * 256 + tid;
        float s = srow[j];
        s_sim[j] = s;
        mn = fminf(mn, s);
        mx = fmaxf(mx, s);
        unsigned m = __ballot_sync(0xffffffffu, __ldg(&labels[j]) == L);
        if (lane == 0) { s_mask[t * 8 + wid] = m; kc += __popc(m); }
    }
    if (lane == 0) atomicAdd(&s_k, kc);
    #pragma unroll
    for (int o = 16; o; o >>= 1) {
        mn = fminf(mn, __shfl_down_sync(0xffffffffu, mn, o));
        mx = fmaxf(mx, __shfl_down_sync(0xffffffffu, mx, o));
    }
    if (lane == 0) { red_f[wid] = mn; red_i[wid] = __float_as_int(mx); }
    __syncthreads();
    if (tid == 0) {
        float a = red_f[0], b = __int_as_float(red_i[0]);
        for (int w2 = 1; w2 < 8; w2++) {
            a = fminf(a, red_f[w2]);
            b = fmaxf(b, __int_as_float(red_i[w2]));
        }
        s_mn = a; s_mx = b;
        s_invw = (float)NB / fmaxf(b - a, 1e-30f);
    }
    __syncthreads();

    const float mnb = s_mn, invw = s_invw;
    const int k = s_k;

    // Pass B: histogram (monotone binning)
    #pragma unroll
    for (int t = 0; t < BSZ / 256; t++) {
        float s = s_sim[t * 256 + tid];
        int b = (int)((s - mnb) * invw);
        b = min(b, NB - 1);
        atomicAdd(&s_hist[b], 1);
    }
    __syncthreads();

    // Suffix scan over 256 groups of 8 bins
    {
        int c = 0;
        #pragma unroll
        for (int i = 0; i < 8; i++) c += s_hist[tid * 8 + i];
        sS[tid] = c;
    }
    __syncthreads();
    #pragma unroll
    for (int off = 1; off < 256; off <<= 1) {
        int v = (tid + off < 256) ? sS[tid + off] : 0;
        __syncthreads();
        sS[tid] += v;
        __syncthreads();
    }
    {
        int St = sS[tid];
        int Sn = (tid < 255) ? sS[tid + 1] : 0;
        if (St >= k && Sn < k) {          // unique crossing thread
            int cum = Sn;
            for (int i = 7; i >= 0; i--) {
                int cnt = s_hist[tid * 8 + i];
                if (cum + cnt >= k) { s_binB = tid * 8 + i; s_above = cum; break; }
                cum += cnt;
            }
        }
    }
    __syncthreads();

    const int binB = s_binB;
    const int r = k - s_above;           // >= 1, usually 1-3

    // Iterative max restricted to bin binB (reference tie semantics)
    float prevS = CUDART_INF_F;
    int   prevI = -1;
    for (int it = 0; it < r; it++) {
        float bs = -CUDART_INF_F;
        int   bi = 0x7fffffff;
        #pragma unroll
        for (int t = 0; t < BSZ / 256; t++) {
            int j = t * 256 + tid;
            float s = s_sim[j];
            int b = (int)((s - mnb) * invw);
            b = min(b, NB - 1);
            if (b != binB) continue;
            bool lt = (s < prevS) || (s == prevS && j > prevI);
            if (lt && (s > bs || (s == bs && j < bi))) { bs = s; bi = j; }
        }
        #pragma unroll
        for (int o = 16; o; o >>= 1) {
            float os = __shfl_down_sync(0xffffffffu, bs, o);
            int   oi = __shfl_down_sync(0xffffffffu, bi, o);
            if (os > bs || (os == bs && oi < bi)) { bs = os; bi = oi; }
        }
        if (lane == 0) { red_f[wid] = bs; red_i[wid] = bi; }
        __syncthreads();
        if (tid == 0) {
            for (int w2 = 1; w2 < 8; w2++) {
                if (red_f[w2] > bs || (red_f[w2] == bs && red_i[w2] < bi)) {
                    bs = red_f[w2]; bi = red_i[w2];
                }
            }
            s_ts = bs; s_ti = bi;
        }
        __syncthreads();
        prevS = s_ts; prevI = s_ti;
    }

    // Classification: interesting = in_topk XOR positive (fp or fn)
    const float ts = s_ts;
    const int   ti = s_ti;
    #pragma unroll
    for (int t = 0; t < BSZ / 256; t++) {
        int j = t * 256 + tid;
        float s = s_sim[j];
        bool topk = (s > ts) || (s == ts && j <= ti);
        bool pos = (s_mask[j >> 5] >> (j & 31)) & 1u;
        if (topk != pos) {
            int slot = atomicAdd(&s_nc, 1);
            if (slot < MAXC) s_cand[slot] = j;
        }
    }
    __syncthreads();

    // Global ranks of candidates: 4 per warp per sweep
    const int nc = min(s_nc, MAXC);
    for (int base = 0; base < nc; base += 32) {
        int q0 = base + wid * 4;
        int jj[4]; float ssv[4]; int cc[4] = {0, 0, 0, 0};
        #pragma unroll
        for (int e = 0; e < 4; e++) {
            int q = q0 + e;
            bool val = q < nc;
            jj[e] = val ? s_cand[q] : -1;
            ssv[e] = val ? s_sim[jj[e]] : CUDART_INF_F;
        }
        for (int m = lane; m < BSZ; m += 32) {
            float v = s_sim[m];
            #pragma unroll
            for (int e = 0; e < 4; e++) {
                cc[e] += (v > ssv[e]) ? 1 : 0;
                cc[e] += (v == ssv[e] && m < jj[e]) ? 1 : 0;
            }
        }
        #pragma unroll
        for (int e = 0; e < 4; e++) {
            #pragma unroll
            for (int o = 16; o; o >>= 1) cc[e] += __shfl_down_sync(0xffffffffu, cc[e], o);
        }
        if (lane == 0) {
            #pragma unroll
            for (int e = 0; e < 4; e++)
                if (q0 + e < nc) s_crank[q0 + e] = cc[e] + 1;
        }
    }
    __syncthreads();

    // Deterministic accumulate: sort candidates by index, then weighted sum
    if (tid == 0) {
        for (int a = 1; a < nc; a++) {
            int cj = s_cand[a], cr = s_crank[a], b2 = a - 1;
            while (b2 >= 0 && s_cand[b2] > cj) {
                s_cand[b2 + 1] = s_cand[b2];
                s_crank[b2 + 1] = s_crank[b2];
                b2--;
            }
            s_cand[b2 + 1] = cj; s_crank[b2 + 1] = cr;
        }
        float kf = (float)k, nk = (float)BSZ - kf;
        float fp = 0.f, fnt = 0.f;
        for (int q = 0; q < nc; q++) {
            int j = s_cand[q];
            float s = s_sim[j];
            float rank = (float)s_crank[q];
            bool pos = (s_mask[j >> 5] >> (j & 31)) & 1u;
            if (!pos) fp  += s * (0.5f + (kf - rank + 1.0f) / kf * 0.5f);
            else      fnt += s * (0.5f + (rank - kf) / nk * 0.5f);
        }
        g_partial[row] = fp - fnt;
    }
}

// ---------------------------------------------------------------------------
// K4: deterministic fixed-order reduction
// ---------------------------------------------------------------------------
__global__ void reduce_kernel(float* __restrict__ out) {
    __shared__ float s[256];
    int tid = threadIdx.x;
    float a = 0.0f;
    #pragma unroll
    for (int i = 0; i < BSZ / 256; i++) a += g_partial[i * 256 + tid];
    s[tid] = a;
    __syncthreads();
    for (int o = 128; o; o >>= 1) {
        if (tid < o) s[tid] += s[tid + o];
        __syncthreads();
    }
    if (tid == 0) out[0] = s[0];
}

// ---------------------------------------------------------------------------
extern "C" void kernel_launch(void* const* d_in, const int* in_sizes, int n_in,
                              void* d_out, int out_size) {
    const float* X      = (const float*)d_in[0];   // batch_reprs [4096,128] f32
    const int*   labels = (const int*)d_in[1];     // batch_labels [4096] i32
    float* out = (float*)d_out;

    cudaFuncSetAttribute(sim_mma_kernel, cudaFuncAttributeMaxDynamicSharedMemorySize, SIM_SMEM);

    prep_kernel<<<BSZ / 8, dim3(32, 8)>>>(X);
    sim_mma_kernel<<<NTRI, 256, SIM_SMEM>>>(labels);
    rank_kernel<<<BSZ, 256>>>(labels);
    reduce_kernel<<<1, 256>>>(out);
}